// round 1
// baseline (speedup 1.0000x reference)
#include <cuda_runtime.h>
#include <stdint.h>

// Problem constants (fixed by the reference setup)
#define Bn 16
#define Pn 784
#define Dn 10000
#define Ln 1000
#define Cn 10

#define WSTRIDE 320   // padded words per row (320*32 = 10240 >= 10000)
#define SEGS    80    // 128-dim segments per row; 80*4 = 320 words
#define WB_COUNT 20   // 320 words / 16 words-per-block
#define CHUNKS  16
#define PCHUNK  49    // 784 / 16

// Scratch (allocation-free: device globals)
__device__ uint32_t g_vbits[Ln * WSTRIDE];   // sign bits of value_weight
__device__ uint32_t g_pbits[Pn * WSTRIDE];   // sign bits of position_weight
__device__ int      g_idx[Bn * Pn];          // level index per (b, pixel)
__device__ float    g_partial[WB_COUNT * Bn * Cn];

// ---------------------------------------------------------------------------
// Kernel 1: compute idx, and pack sign bits of both bipolar tables.
// Bit layout (permuted, consistent across tables): word w, bit l  <->
//   dim d = (w>>2)*128 + l*4 + (w&3).   Padding dims pack as 0.
// ---------------------------------------------------------------------------
__global__ void pack_kernel(const float* __restrict__ x,
                            const float* __restrict__ posw,
                            const float* __restrict__ valw)
{
    const int tid     = blockIdx.x * blockDim.x + threadIdx.x;
    const int nthread = gridDim.x * blockDim.x;

    // --- level index: idx = clamp(rint(x*999), 0, 999)  (rintf = half-to-even)
    for (int i = tid; i < Bn * Pn; i += nthread) {
        int q = (int)rintf(x[i] * 999.0f);
        q = min(max(q, 0), Ln - 1);
        g_idx[i] = q;
    }

    // --- sign packing: one warp-task = (table row, 128-dim segment)
    const int lane   = threadIdx.x & 31;
    const int warpId = tid >> 5;
    const int nWarps = nthread >> 5;
    const int totalTasks = (Ln + Pn) * SEGS;

    for (int task = warpId; task < totalTasks; task += nWarps) {
        int row, s;
        const float* src;
        uint32_t* dst;
        if (task < Ln * SEGS) {
            row = task / SEGS; s = task - row * SEGS;
            src = valw + (size_t)row * Dn;
            dst = g_vbits + row * WSTRIDE;
        } else {
            int t2 = task - Ln * SEGS;
            row = t2 / SEGS; s = t2 - row * SEGS;
            src = posw + (size_t)row * Dn;
            dst = g_pbits + row * WSTRIDE;
        }
        const int d0 = s * 128 + lane * 4;   // Dn % 4 == 0: float4 fully valid or fully OOB
        uint32_t sb0 = 0, sb1 = 0, sb2 = 0, sb3 = 0;
        if (d0 < Dn) {
            float4 v = *reinterpret_cast<const float4*>(src + d0);
            sb0 = __float_as_uint(v.x) >> 31;
            sb1 = __float_as_uint(v.y) >> 31;
            sb2 = __float_as_uint(v.z) >> 31;
            sb3 = __float_as_uint(v.w) >> 31;
        }
        uint32_t b0 = __ballot_sync(0xffffffffu, sb0);
        uint32_t b1 = __ballot_sync(0xffffffffu, sb1);
        uint32_t b2 = __ballot_sync(0xffffffffu, sb2);
        uint32_t b3 = __ballot_sync(0xffffffffu, sb3);
        if (lane == 0) {
            *reinterpret_cast<uint4*>(dst + s * 4) = make_uint4(b0, b1, b2, b3);
        }
    }
}

// ---------------------------------------------------------------------------
// Kernel 2: per (batch, 16-word block) CTA.
//   Thread (chunk = tid&15, wl = tid>>4) accumulates, for its word w and its
//   49-pixel chunk, bit-sliced per-dim counts of negative products
//   (XOR of sign bits), then shuffle-reduces across chunks, thresholds
//   count < 392  (i.e. s = 784-2c > 0)  to get enc bits, and computes the
//   classify partial sums for this 512-dim slab. No atomics; fixed-order
//   reductions -> deterministic.
// ---------------------------------------------------------------------------
__global__ void __launch_bounds__(256) hdc_main_kernel(const float* __restrict__ cw)
{
    const int b  = blockIdx.x / WB_COUNT;
    const int wb = blockIdx.x % WB_COUNT;
    const int tid = threadIdx.x;

    __shared__ int      sIdx[Pn];
    __shared__ uint32_t encS[16];
    __shared__ float    redS[256];

    for (int i = tid; i < Pn; i += 256) sIdx[i] = g_idx[b * Pn + i];
    __syncthreads();

    const int chunk = tid & 15;
    const int wl    = tid >> 4;
    const int w     = wb * 16 + wl;

    uint32_t c[10];
#pragma unroll
    for (int j = 0; j < 10; j++) c[j] = 0u;

    const int p0 = chunk * PCHUNK;
    const uint32_t* __restrict__ pb = g_pbits + p0 * WSTRIDE + w;

#pragma unroll 7
    for (int i = 0; i < PCHUNK; i++) {
        int lvl    = sIdx[p0 + i];
        uint32_t v = __ldg(g_vbits + lvl * WSTRIDE + w);
        uint32_t q = __ldg(pb + i * WSTRIDE);
        uint32_t carry = v ^ q;                 // 1 where product is -1
        // ripple-add 1 bit into 6-plane counters (max 49 < 64)
#pragma unroll
        for (int j = 0; j < 6; j++) {
            uint32_t nc = c[j] ^ carry;
            carry = c[j] & carry;
            c[j] = nc;
        }
    }

    // reduce the 16 chunk-counters within each 16-lane half (bit-sliced add)
#pragma unroll
    for (int off = 8; off >= 1; off >>= 1) {
        uint32_t t[10];
#pragma unroll
        for (int j = 0; j < 10; j++) t[j] = __shfl_down_sync(0xffffffffu, c[j], off, 16);
        uint32_t carry = 0;
#pragma unroll
        for (int j = 0; j < 10; j++) {
            uint32_t a = c[j], bb = t[j];
            c[j]  = a ^ bb ^ carry;
            carry = (a & bb) | (carry & (a ^ bb));
        }
    }

    if (chunk == 0) {
        // per-dim: enc = +1 iff count < 392 (392 = 0b0110001000)
        uint32_t eq = ~0u, lt = 0u;
        eq &= ~c[9];
        lt |= eq & ~c[8]; eq &= c[8];
        lt |= eq & ~c[7]; eq &= c[7];
        eq &= ~c[6]; eq &= ~c[5]; eq &= ~c[4];
        lt |= eq & ~c[3];
        encS[wl] = lt;                          // bit set -> enc = +1
    }
    __syncthreads();

    // classify partials for this 512-dim slab: thread (class = tid%10, slot = tid/10)
    float acc = 0.0f;
    if (tid < 250) {
        const int cc   = tid % 10;
        const int slot = tid / 10;
        const float* __restrict__ wrow = cw + cc * Dn;
        for (int j = slot; j < 512; j += 25) {
            int wl2 = j >> 5, l = j & 31;
            int wg  = wb * 16 + wl2;
            int d   = (wg >> 2) * 128 + (l << 2) + (wg & 3);
            if (d < Dn) {
                float wt = __ldg(wrow + d);
                acc += ((encS[wl2] >> l) & 1u) ? wt : -wt;
            }
        }
    }
    redS[tid] = acc;
    __syncthreads();

    if (tid < 10) {
        float s = 0.0f;
#pragma unroll
        for (int slot = 0; slot < 25; slot++) s += redS[tid + slot * 10];
        g_partial[(wb * Bn + b) * Cn + tid] = s;
    }
}

// ---------------------------------------------------------------------------
// Kernel 3: deterministic final reduction over the 20 word-blocks.
// ---------------------------------------------------------------------------
__global__ void finalize_kernel(float* __restrict__ out)
{
    int i = threadIdx.x;
    if (i < Bn * Cn) {
        float s = 0.0f;
#pragma unroll
        for (int wb = 0; wb < WB_COUNT; wb++) s += g_partial[wb * Bn * Cn + i];
        out[i] = s;
    }
}

// ---------------------------------------------------------------------------
extern "C" void kernel_launch(void* const* d_in, const int* in_sizes, int n_in,
                              void* d_out, int out_size)
{
    const float* x    = (const float*)d_in[0];   // [16,28,28]
    const float* posw = (const float*)d_in[1];   // [784,10000]
    const float* valw = (const float*)d_in[2];   // [1000,10000]
    const float* cw   = (const float*)d_in[3];   // [10,10000]
    float* out = (float*)d_out;                  // [16,10]

    pack_kernel<<<1184, 256>>>(x, posw, valw);
    hdc_main_kernel<<<Bn * WB_COUNT, 256>>>(cw);
    finalize_kernel<<<1, 192>>>(out);
}

// round 3
// speedup vs baseline: 1.1822x; 1.1822x over previous
#include <cuda_runtime.h>
#include <stdint.h>

// Problem constants (fixed by the reference setup)
#define Bn 16
#define Pn 784
#define Dn 10000
#define Ln 1000
#define Cn 10

#define WSTRIDE 320   // padded words per row (320*32 = 10240 >= 10000)
#define NSLAB   10    // 10 slabs of 32 words each
#define PXW     98    // pixels per warp (8 warps * 98 = 784)

// Scratch (allocation-free: device globals)
__device__ uint32_t g_vbits[Ln * WSTRIDE];   // sign bits of value_weight
__device__ uint32_t g_pbits[Pn * WSTRIDE];   // sign bits of position_weight
__device__ int      g_idx[Bn * Pn];          // level index per (b, pixel)
__device__ float    g_partial[NSLAB * Bn * Cn];

// ---------------------------------------------------------------------------
// Kernel 1: compute idx, pack sign bits of both bipolar tables.
// Bit layout: word w, bit l  <->  dim d = (w>>2)*128 + l*4 + (w&3).
// Each warp-task covers 512 dims (16 words): 4 independent float4 loads per
// thread (MLP=4), then 16 ballots, then one coalesced 64B store.
// ---------------------------------------------------------------------------
__global__ void pack_kernel(const float* __restrict__ x,
                            const float* __restrict__ posw,
                            const float* __restrict__ valw)
{
    const int tid     = blockIdx.x * blockDim.x + threadIdx.x;
    const int nthread = gridDim.x * blockDim.x;

    // level index: idx = clamp(rint(x*999), 0, 999)  (rintf = half-to-even)
    for (int i = tid; i < Bn * Pn; i += nthread) {
        int q = (int)rintf(x[i] * 999.0f);
        g_idx[i] = min(max(q, 0), Ln - 1);
    }

    const int lane   = threadIdx.x & 31;
    const int warpId = tid >> 5;
    const int nWarps = nthread >> 5;
    const int totalTasks = (Ln + Pn) * 20;   // 20 x 512-dim tasks per row

    for (int task = warpId; task < totalTasks; task += nWarps) {
        int row = task / 20;
        int s   = task - row * 20;
        const float* src;
        uint32_t* dst;
        if (row < Ln) {
            src = valw + (size_t)row * Dn;
            dst = g_vbits + row * WSTRIDE;
        } else {
            src = posw + (size_t)(row - Ln) * Dn;
            dst = g_pbits + (row - Ln) * WSTRIDE;
        }

        uint32_t nib[4];
#pragma unroll
        for (int sub = 0; sub < 4; sub++) {
            int d0 = s * 512 + sub * 128 + lane * 4;  // multiple of 4; valid iff d0 < Dn
            uint32_t n = 0;
            if (d0 < Dn) {
                float4 v = *reinterpret_cast<const float4*>(src + d0);
                n =  (__float_as_uint(v.x) >> 31)
                  | ((__float_as_uint(v.y) >> 31) << 1)
                  | ((__float_as_uint(v.z) >> 31) << 2)
                  | ((__float_as_uint(v.w) >> 31) << 3);
            }
            nib[sub] = n;
        }

        uint32_t myword = 0;
#pragma unroll
        for (int sub = 0; sub < 4; sub++) {
#pragma unroll
            for (int k = 0; k < 4; k++) {
                uint32_t bal = __ballot_sync(0xffffffffu, (nib[sub] >> k) & 1u);
                if (lane == sub * 4 + k) myword = bal;   // word w = s*16 + sub*4 + k
            }
        }
        if (lane < 16) dst[s * 16 + lane] = myword;      // coalesced 64B
    }
}

// ---------------------------------------------------------------------------
__device__ __forceinline__ void fadd(uint32_t a, uint32_t b, uint32_t cin,
                                     uint32_t& s, uint32_t& cout)
{
    uint32_t t = a ^ b;
    s    = t ^ cin;
    cout = (a & b) | (cin & t);
}

// ---------------------------------------------------------------------------
// Kernel 2: CTA = (batch, 32-word slab). Warp lane = word within slab so all
// bit-table loads are 128B fully-coalesced. Each warp accumulates 98 pixels
// via a 7:3 CSA compressor into 7 bit-planes; warps reduce through smem;
// threshold gives enc bits; classify partials computed per slab.
// Fixed-order reductions, no atomics -> deterministic.
// ---------------------------------------------------------------------------
__global__ void __launch_bounds__(256) hdc_main_kernel(const float* __restrict__ cw)
{
    const int b    = blockIdx.x / NSLAB;
    const int slab = blockIdx.x - b * NSLAB;
    const int tid  = threadIdx.x;
    const int lane = tid & 31;
    const int warp = tid >> 5;

    __shared__ int      sIdx[Pn];
    __shared__ uint32_t sRed[8][7][33];   // padded: kills bank-stride conflicts
    __shared__ uint32_t encW[32];
    __shared__ float    redS[256];

    for (int i = tid; i < Pn; i += 256) sIdx[i] = g_idx[b * Pn + i];
    __syncthreads();

    const int w = slab * 32 + lane;

    uint32_t c[7];
#pragma unroll
    for (int j = 0; j < 7; j++) c[j] = 0u;

    const int p0 = warp * PXW;
    const uint32_t* __restrict__ vb = g_vbits + w;
    const uint32_t* __restrict__ pb = g_pbits + w;

    for (int g = 0; g < 14; g++) {            // 14 groups of 7 pixels
        const int pbase = p0 + g * 7;
        uint32_t t[7];
#pragma unroll
        for (int k = 0; k < 7; k++) {
            int lvl = sIdx[pbase + k];
            t[k] = __ldg(vb + lvl * WSTRIDE) ^ __ldg(pb + (pbase + k) * WSTRIDE);
        }
        // 7:3 compressor -> (s3, s4, c4) with weights 1,2,4
        uint32_t s1, c1, s2, c2, s3, c3, s4, c4;
        fadd(t[0], t[1], t[2], s1, c1);
        fadd(t[3], t[4], t[5], s2, c2);
        fadd(s1,  s2,  t[6],  s3, c3);
        fadd(c1,  c2,  c3,    s4, c4);
        // merge 3-bit value into the 7-plane counter
        uint32_t carry = c[0] & s3; c[0] ^= s3;
        uint32_t s, co;
        fadd(c[1], s4, carry, s, co); c[1] = s; carry = co;
        fadd(c[2], c4, carry, s, co); c[2] = s; carry = co;
#pragma unroll
        for (int j = 3; j < 7; j++) { uint32_t nc = c[j] ^ carry; carry &= c[j]; c[j] = nc; }
    }

#pragma unroll
    for (int j = 0; j < 7; j++) sRed[warp][j][lane] = c[j];
    __syncthreads();

    if (warp == 0) {
        uint32_t a[10];
#pragma unroll
        for (int j = 0; j < 7; j++) a[j] = sRed[0][j][lane];
        a[7] = a[8] = a[9] = 0u;
#pragma unroll
        for (int wu = 1; wu < 8; wu++) {
            uint32_t carry = 0u;
#pragma unroll
            for (int j = 0; j < 7; j++) {
                uint32_t s, co;
                fadd(a[j], sRed[wu][j][lane], carry, s, co);
                a[j] = s; carry = co;
            }
#pragma unroll
            for (int j = 7; j < 10; j++) { uint32_t nc = a[j] ^ carry; carry &= a[j]; a[j] = nc; }
        }
        // enc = +1 iff count < 392 (392 = 0b0110001000)
        uint32_t eq = ~0u, lt = 0u;
        eq &= ~a[9];
        lt |= eq & ~a[8]; eq &= a[8];
        lt |= eq & ~a[7]; eq &= a[7];
        eq &= ~a[6]; eq &= ~a[5]; eq &= ~a[4];
        lt |= eq & ~a[3];
        encW[lane] = lt;                       // bit set -> enc = +1
    }
    __syncthreads();

    // classify partials for this 1024-dim slab
    float acc = 0.0f;
    if (tid < 250) {
        const int cc   = tid % 10;
        const int slot = tid / 10;
        const float* __restrict__ wrow = cw + cc * Dn;
        for (int j = slot; j < 1024; j += 25) {
            int wl2 = j >> 5, l = j & 31;
            int wg  = slab * 32 + wl2;
            int d   = (wg >> 2) * 128 + (l << 2) + (wg & 3);
            if (d < Dn) {
                float wt = __ldg(wrow + d);
                acc += ((encW[wl2] >> l) & 1u) ? wt : -wt;
            }
        }
    }
    redS[tid] = acc;
    __syncthreads();

    if (tid < 10) {
        float s = 0.0f;
#pragma unroll
        for (int slot = 0; slot < 25; slot++) s += redS[tid + slot * 10];
        g_partial[(slab * Bn + b) * Cn + tid] = s;
    }
}

// ---------------------------------------------------------------------------
// Kernel 3: deterministic final reduction over the 10 slabs.
// ---------------------------------------------------------------------------
__global__ void finalize_kernel(float* __restrict__ out)
{
    int i = threadIdx.x;
    if (i < Bn * Cn) {
        float s = 0.0f;
#pragma unroll
        for (int sl = 0; sl < NSLAB; sl++) s += g_partial[sl * Bn * Cn + i];
        out[i] = s;
    }
}

// ---------------------------------------------------------------------------
extern "C" void kernel_launch(void* const* d_in, const int* in_sizes, int n_in,
                              void* d_out, int out_size)
{
    const float* x    = (const float*)d_in[0];   // [16,28,28]
    const float* posw = (const float*)d_in[1];   // [784,10000]
    const float* valw = (const float*)d_in[2];   // [1000,10000]
    const float* cw   = (const float*)d_in[3];   // [10,10000]
    float* out = (float*)d_out;                  // [16,10]

    pack_kernel<<<1184, 256>>>(x, posw, valw);
    hdc_main_kernel<<<Bn * NSLAB, 256>>>(cw);
    finalize_kernel<<<1, 192>>>(out);
}